// round 5
// baseline (speedup 1.0000x reference)
#include <cuda_runtime.h>

typedef unsigned long long ull;

#define BATCH 2
#define CHAN  128
#define NTOK  784
#define INV_T (1.0f / 11.313708498984761f)
#define LOG2E 1.4426950408889634f
#define ABS2_MASK 0x7FFFFFFF7FFFFFFFULL
#define INVC2_BITS 0x3C0000003C000000ULL   /* packed (1/128, 1/128) */

// ---------------------------------------------------------------------------
// Packed fp32x2 helpers (sm_100+; ptxas never emits these from plain C++)
// ---------------------------------------------------------------------------
__device__ __forceinline__ ull f32x2_add(ull a, ull b) {
    ull r; asm("add.rn.f32x2 %0, %1, %2;" : "=l"(r) : "l"(a), "l"(b)); return r;
}
__device__ __forceinline__ ull f32x2_mul(ull a, ull b) {
    ull r; asm("mul.rn.f32x2 %0, %1, %2;" : "=l"(r) : "l"(a), "l"(b)); return r;
}
__device__ __forceinline__ ull f32x2_fma(ull a, ull b, ull c) {
    ull r; asm("fma.rn.f32x2 %0, %1, %2, %3;" : "=l"(r) : "l"(a), "l"(b), "l"(c)); return r;
}
__device__ __forceinline__ ull dup2(float x) {
    ull r; asm("mov.b64 %0, {%1, %1};" : "=l"(r) : "f"(x)); return r;
}
__device__ __forceinline__ void unpack2(ull v, float& lo, float& hi) {
    asm("mov.b64 {%0, %1}, %2;" : "=f"(lo), "=f"(hi) : "l"(v));
}

// ---------------------------------------------------------------------------
// Kernel 1: L1-distance logits, packed f32x2.
// logits[b,k,q] = (1/C) * sum_c | q[b,c,q]/T - k[b,c,k] |
// Block: 64(k) x 64(q) tile, 256 threads, thread-tile 4k x 4q (2 q-pairs).
// k values stored NEGATED + duplicated in smem so inner op is:
//   d2 = add.f32x2(q2, nk2);  d2 &= |mask| (2x LOP3, alu pipe);  acc2 += d2
// -> 1 fma-pipe instr + 1 alu-pipe instr per element (was 2 fma-pipe).
// ---------------------------------------------------------------------------
__global__ void l1_logits_kernel(const float* __restrict__ q,
                                 const float* __restrict__ k,
                                 float* __restrict__ attn)
{
    const int b  = blockIdx.z;
    const int k0 = blockIdx.y * 64;
    const int q0 = blockIdx.x * 64;

    __shared__ __align__(16) float qs[8][64];
    __shared__ __align__(16) ull   nkd[8][64];   // duplicated (-k,-k) pairs

    const int tid = threadIdx.x;
    const int tx  = tid & 15;           // q-group: 4 q = 2 pairs
    const int ty  = tid >> 4;           // k-group: 4 k

    const float* qb = q + (size_t)b * CHAN * NTOK;
    const float* kb = k + (size_t)b * CHAN * NTOK;

    ull acc[4][2];
    #pragma unroll
    for (int j = 0; j < 4; j++) { acc[j][0] = 0ULL; acc[j][1] = 0ULL; }

    for (int c0 = 0; c0 < CHAN; c0 += 8) {
        // load 8x64 chunks: q scaled, k negated+duplicated. 2 each per thread.
        #pragma unroll
        for (int r = 0; r < 2; r++) {
            int i   = tid + r * 256;
            int cc  = i >> 6;
            int col = i & 63;
            int qi = q0 + col; if (qi >= NTOK) qi = NTOK - 1;   // clamped lanes never stored
            int ki = k0 + col; if (ki >= NTOK) ki = NTOK - 1;
            qs[cc][col]  = qb[(size_t)(c0 + cc) * NTOK + qi] * INV_T;
            float kv     = kb[(size_t)(c0 + cc) * NTOK + ki];
            nkd[cc][col] = dup2(-kv);
        }
        __syncthreads();

        #pragma unroll
        for (int cc = 0; cc < 8; cc++) {
            ulonglong2 qp  = *(const ulonglong2*)&qs[cc][tx * 4];   // 4 q = 2 packed pairs
            ull q2[2]; q2[0] = qp.x; q2[1] = qp.y;
            ulonglong2 k01 = *(const ulonglong2*)&nkd[cc][ty * 4];
            ulonglong2 k23 = *(const ulonglong2*)&nkd[cc][ty * 4 + 2];
            ull kd[4]; kd[0] = k01.x; kd[1] = k01.y; kd[2] = k23.x; kd[3] = k23.y;

            #pragma unroll
            for (int j = 0; j < 4; j++) {
                #pragma unroll
                for (int p = 0; p < 2; p++) {
                    ull d = f32x2_add(q2[p], kd[j]);   // q/T - k  (packed)
                    d &= ABS2_MASK;                    // |.| on both halves (alu pipe)
                    acc[j][p] = f32x2_add(acc[j][p], d);
                }
            }
        }
        __syncthreads();
    }

    float* ab = attn + (size_t)b * NTOK * NTOK;
    const bool qok = (q0 + tx * 4) < NTOK;   // 784 % 4 == 0: group is all-in or all-out
    #pragma unroll
    for (int j = 0; j < 4; j++) {
        int kk = k0 + ty * 4 + j;
        if (kk < NTOK && qok) {
            ull r0 = f32x2_mul(acc[j][0], (ull)INVC2_BITS);
            ull r1 = f32x2_mul(acc[j][1], (ull)INVC2_BITS);
            float4 f;
            unpack2(r0, f.x, f.y);
            unpack2(r1, f.z, f.w);
            *(float4*)&ab[(size_t)kk * NTOK + q0 + tx * 4] = f;
        }
    }
}

// ---------------------------------------------------------------------------
// Kernel 2: in-place softmax over last dim (q). One WARP per row, 8 rows/block.
// ---------------------------------------------------------------------------
__global__ void softmax_kernel(float* __restrict__ attn)
{
    const int row  = blockIdx.x * 8 + (threadIdx.x >> 5);   // 196*8 = 1568 exact
    const int lane = threadIdx.x & 31;
    float* a = attn + (size_t)row * NTOK;

    float v[25];
    float mx = -1e30f;
    #pragma unroll
    for (int i = 0; i < 25; i++) {
        int idx = lane + i * 32;
        v[i] = (idx < NTOK) ? a[idx] : -1e30f;
        mx = fmaxf(mx, v[i]);
    }
    #pragma unroll
    for (int o = 16; o; o >>= 1)
        mx = fmaxf(mx, __shfl_xor_sync(0xffffffffu, mx, o));

    float s = 0.0f;
    #pragma unroll
    for (int i = 0; i < 25; i++) {
        v[i] = exp2f((v[i] - mx) * LOG2E);   // OOB lanes -> 0
        s += v[i];
    }
    #pragma unroll
    for (int o = 16; o; o >>= 1)
        s += __shfl_xor_sync(0xffffffffu, s, o);

    float inv = __frcp_rn(s);
    #pragma unroll
    for (int i = 0; i < 25; i++) {
        int idx = lane + i * 32;
        if (idx < NTOK) a[idx] = v[i] * inv;
    }
}

// ---------------------------------------------------------------------------
// Kernel 3: out[b,c,k] = sum_q v[b,c,q] * attn[b,k,q]   (packed f32x2 over k)
// Tile 64(k) x 32(c), 256 threads, thread-tile 4k(2 pairs) x 2c.
// attn tile stored TRANSPOSED [q][k] so k-pairs are contiguous ulls;
// v stored pre-duplicated as (v,v) ull so the FMA multiplier is ready-made.
// Grid: 13 x 4 x 2 = 104 blocks -> one clean wave.
// ---------------------------------------------------------------------------
__global__ void out_gemm_kernel(const float* __restrict__ v,
                                const float* __restrict__ attn,
                                float* __restrict__ out)
{
    const int b  = blockIdx.z;
    const int k0 = blockIdx.x * 64;
    const int c0 = blockIdx.y * 32;

    __shared__ __align__(16) float at[32][68];   // [q][k], pad 68 (16B rows)
    __shared__ __align__(16) ull   vd[32][32];   // [c][q], duplicated pairs

    const int tid = threadIdx.x;
    const int tx  = tid & 15;           // k-group: 4 k = 2 pairs
    const int ty  = tid >> 4;           // c-group: 2 c

    const float* vb = v    + (size_t)b * CHAN * NTOK;
    const float* ab = attn + (size_t)b * NTOK * NTOK;

    ull acc[2][2];
    acc[0][0] = acc[0][1] = acc[1][0] = acc[1][1] = 0ULL;

    for (int q0 = 0; q0 < NTOK; q0 += 32) {
        // attn tile [k0:k0+64, q0:q0+32] -> transposed at[qq][kk]. 8/thread.
        #pragma unroll
        for (int r = 0; r < 8; r++) {
            int i  = tid + r * 256;
            int kk = i >> 5;
            int qq = i & 31;
            int kr = k0 + kk; if (kr >= NTOK) kr = NTOK - 1;    // never stored
            int qg = q0 + qq;
            at[qq][kk] = (qg < NTOK) ? ab[(size_t)kr * NTOK + qg] : 0.0f;
        }
        // v tile [c0:c0+32, q0:q0+32] -> duplicated ull. 4/thread.
        #pragma unroll
        for (int r = 0; r < 4; r++) {
            int i  = tid + r * 256;
            int cc = i >> 5;
            int qq = i & 31;
            int qg = q0 + qq; if (qg >= NTOK) qg = NTOK - 1;    // paired at==0
            vd[cc][qq] = dup2(vb[(size_t)(c0 + cc) * NTOK + qg]);
        }
        __syncthreads();

        #pragma unroll
        for (int qq = 0; qq < 32; qq++) {
            ull a0 = *(const ull*)&at[qq][tx * 4];
            ull a1 = *(const ull*)&at[qq][tx * 4 + 2];
            ull v0 = vd[ty * 2 + 0][qq];
            ull v1 = vd[ty * 2 + 1][qq];
            acc[0][0] = f32x2_fma(v0, a0, acc[0][0]);
            acc[0][1] = f32x2_fma(v0, a1, acc[0][1]);
            acc[1][0] = f32x2_fma(v1, a0, acc[1][0]);
            acc[1][1] = f32x2_fma(v1, a1, acc[1][1]);
        }
        __syncthreads();
    }

    float* ob = out + (size_t)b * CHAN * NTOK;
    const int kg = k0 + tx * 4;
    if (kg < NTOK) {                    // 784 % 4 == 0: all-or-none per group
        #pragma unroll
        for (int j = 0; j < 2; j++) {
            int cc = c0 + ty * 2 + j;
            float4 f;
            unpack2(acc[j][0], f.x, f.y);
            unpack2(acc[j][1], f.z, f.w);
            *(float4*)&ob[(size_t)cc * NTOK + kg] = f;
        }
    }
}

// ---------------------------------------------------------------------------
extern "C" void kernel_launch(void* const* d_in, const int* in_sizes, int n_in,
                              void* d_out, int out_size)
{
    const float* q = (const float*)d_in[0];
    const float* k = (const float*)d_in[1];
    const float* v = (const float*)d_in[2];

    float* out_ptr  = (float*)d_out;                         // [B, C, N]
    float* attn_ptr = out_ptr + (size_t)BATCH * CHAN * NTOK; // [B, N, N]

    dim3 g1((NTOK + 63) / 64, (NTOK + 63) / 64, BATCH);      // 13 x 13 x 2
    l1_logits_kernel<<<g1, 256>>>(q, k, attn_ptr);

    softmax_kernel<<<(BATCH * NTOK) / 8, 256>>>(attn_ptr);   // 196 blocks

    dim3 g3((NTOK + 63) / 64, CHAN / 32, BATCH);             // 13 x 4 x 2
    out_gemm_kernel<<<g3, 256>>>(v, attn_ptr, out_ptr);
}

// round 10
// speedup vs baseline: 1.3293x; 1.3293x over previous
#include <cuda_runtime.h>

typedef unsigned long long ull;

#define BATCH 2
#define CHAN  128
#define NTOK  784
#define SPLITS 4
#define QSPAN (NTOK / SPLITS)        /* 196 */
#define QCHUNK 28                    /* 196 = 7 * 28 */
#define INV_T (1.0f / 11.313708498984761f)
#define INV_C (1.0f / 128.0f)
#define LOG2E 1.4426950408889634f

// split-q partial sums for the output GEMM: [SPLITS][B][C][N]
__device__ float g_partial[SPLITS * BATCH * CHAN * NTOK];

// ---------------------------------------------------------------------------
// Packed fp32x2 helpers
// ---------------------------------------------------------------------------
__device__ __forceinline__ ull f32x2_fma(ull a, ull b, ull c) {
    ull r; asm("fma.rn.f32x2 %0, %1, %2, %3;" : "=l"(r) : "l"(a), "l"(b), "l"(c)); return r;
}
__device__ __forceinline__ ull dup2(float x) {
    ull r; asm("mov.b64 %0, {%1, %1};" : "=l"(r) : "f"(x)); return r;
}
__device__ __forceinline__ void unpack2(ull v, float& lo, float& hi) {
    asm("mov.b64 {%0, %1}, %2;" : "=f"(lo), "=f"(hi) : "l"(v));
}

// ---------------------------------------------------------------------------
// Kernel 1: L1-distance logits (scalar FADD, abs as free src modifier).
// logits[b,k,q] = (1/C) * sum_c | q[b,c,q]/T - k[b,c,k] |
// Tile 64(q) x 32(k), 256 threads, thread-tile 4q x 2k.
// Grid 13 x 25 x 2 = 650 blocks -> ~4.4 blocks/SM, ~35 warps/SM.
// ---------------------------------------------------------------------------
__global__ void l1_logits_kernel(const float* __restrict__ q,
                                 const float* __restrict__ k,
                                 float* __restrict__ attn)
{
    const int b  = blockIdx.z;
    const int q0 = blockIdx.x * 64;
    const int k0 = blockIdx.y * 32;

    __shared__ __align__(16) float qs[16][64];
    __shared__ __align__(16) float ks[16][32];

    const int tid = threadIdx.x;        // 0..255
    const int tx  = tid & 15;           // q-group: 4 q
    const int ty  = tid >> 4;           // k-group: 2 k

    const float* qb = q + (size_t)b * CHAN * NTOK;
    const float* kb = k + (size_t)b * CHAN * NTOK;

    float acc[2][4] = {};

    for (int c0 = 0; c0 < CHAN; c0 += 16) {
        // q chunk: 16x64 = 1024 floats, 4/thread
        #pragma unroll
        for (int r = 0; r < 4; r++) {
            int i   = tid + r * 256;
            int cc  = i >> 6;
            int col = i & 63;
            int qi = q0 + col; if (qi >= NTOK) qi = NTOK - 1;   // clamped lanes never stored
            qs[cc][col] = qb[(size_t)(c0 + cc) * NTOK + qi] * INV_T;
        }
        // k chunk: 16x32 = 512 floats, 2/thread
        #pragma unroll
        for (int r = 0; r < 2; r++) {
            int i   = tid + r * 256;
            int cc  = i >> 5;
            int col = i & 31;
            int ki = k0 + col; if (ki >= NTOK) ki = NTOK - 1;
            ks[cc][col] = kb[(size_t)(c0 + cc) * NTOK + ki];
        }
        __syncthreads();

        #pragma unroll
        for (int cc = 0; cc < 16; cc++) {
            float rq[4], rk[2];
            #pragma unroll
            for (int i = 0; i < 4; i++) rq[i] = qs[cc][tx * 4 + i];
            #pragma unroll
            for (int j = 0; j < 2; j++) rk[j] = ks[cc][ty * 2 + j];
            #pragma unroll
            for (int j = 0; j < 2; j++)
                #pragma unroll
                for (int i = 0; i < 4; i++)
                    acc[j][i] += fabsf(rq[i] - rk[j]);
        }
        __syncthreads();
    }

    float* ab = attn + (size_t)b * NTOK * NTOK;
    const int qg = q0 + tx * 4;
    if (qg < NTOK) {                            // 784 % 4 == 0: all-or-none
        #pragma unroll
        for (int j = 0; j < 2; j++) {
            int kk = k0 + ty * 2 + j;
            if (kk < NTOK) {
                float4 f;
                f.x = acc[j][0] * INV_C;
                f.y = acc[j][1] * INV_C;
                f.z = acc[j][2] * INV_C;
                f.w = acc[j][3] * INV_C;
                *(float4*)&ab[(size_t)kk * NTOK + qg] = f;
            }
        }
    }
}

// ---------------------------------------------------------------------------
// Kernel 2: in-place softmax over last dim (q). One WARP per row, 8 rows/block.
// ---------------------------------------------------------------------------
__global__ void softmax_kernel(float* __restrict__ attn)
{
    const int row  = blockIdx.x * 8 + (threadIdx.x >> 5);   // 196*8 = 1568 exact
    const int lane = threadIdx.x & 31;
    float* a = attn + (size_t)row * NTOK;

    float v[25];
    float mx = -1e30f;
    #pragma unroll
    for (int i = 0; i < 25; i++) {
        int idx = lane + i * 32;
        v[i] = (idx < NTOK) ? a[idx] : -1e30f;
        mx = fmaxf(mx, v[i]);
    }
    #pragma unroll
    for (int o = 16; o; o >>= 1)
        mx = fmaxf(mx, __shfl_xor_sync(0xffffffffu, mx, o));

    float s = 0.0f;
    #pragma unroll
    for (int i = 0; i < 25; i++) {
        v[i] = exp2f((v[i] - mx) * LOG2E);   // OOB lanes -> 0
        s += v[i];
    }
    #pragma unroll
    for (int o = 16; o; o >>= 1)
        s += __shfl_xor_sync(0xffffffffu, s, o);

    float inv = __frcp_rn(s);
    #pragma unroll
    for (int i = 0; i < 25; i++) {
        int idx = lane + i * 32;
        if (idx < NTOK) a[idx] = v[i] * inv;
    }
}

// ---------------------------------------------------------------------------
// Kernel 3a: partial[s][b,c,k] = sum_{q in split s} v[b,c,q] * attn[b,k,q]
// Packed f32x2 over k. Tile 64(k) x 32(c), 256 threads, thread 4k(2 pairs) x 2c.
// Grid 13 x 4 x (B*SPLITS=8) = 416 blocks -> 2.8 blocks/SM, ~22 warps/SM.
// attn tile stored transposed [q][k] (float4-aligned rows), v pre-duplicated.
// ---------------------------------------------------------------------------
__global__ void out_gemm_partial_kernel(const float* __restrict__ v,
                                        const float* __restrict__ attn)
{
    const int bz = blockIdx.z;
    const int b  = bz >> 2;             // batch
    const int s  = bz & 3;              // split
    const int k0 = blockIdx.x * 64;
    const int c0 = blockIdx.y * 32;
    const int qbase = s * QSPAN;

    __shared__ __align__(16) float at[QCHUNK][68];   // [q][k], 272B rows (16B mult)
    __shared__ __align__(16) ull   vd[32][QCHUNK];   // [c][q], duplicated pairs

    const int tid = threadIdx.x;
    const int tx  = tid & 15;           // k-group: 4 k = 2 pairs
    const int ty  = tid >> 4;           // c-group: 2 c

    const float* vb = v    + (size_t)b * CHAN * NTOK;
    const float* ab = attn + (size_t)b * NTOK * NTOK;

    ull acc[2][2];
    acc[0][0] = acc[0][1] = acc[1][0] = acc[1][1] = 0ULL;

    for (int qc = 0; qc < QSPAN; qc += QCHUNK) {
        const int q0 = qbase + qc;
        // attn tile 64k x 28q -> transposed. 1792 elems, 7/thread.
        #pragma unroll
        for (int r = 0; r < 7; r++) {
            int i  = tid + r * 256;
            int kk = i / QCHUNK;
            int qq = i - kk * QCHUNK;
            int kr = k0 + kk; if (kr >= NTOK) kr = NTOK - 1;    // never stored
            at[qq][kk] = ab[(size_t)kr * NTOK + q0 + qq];
        }
        // v tile 32c x 28q -> duplicated ull. 896 elems, <=4/thread.
        #pragma unroll
        for (int r = 0; r < 4; r++) {
            int i = tid + r * 256;
            if (i < 32 * QCHUNK) {
                int cc = i / QCHUNK;
                int qq = i - cc * QCHUNK;
                vd[cc][qq] = dup2(vb[(size_t)(c0 + cc) * NTOK + q0 + qq]);
            }
        }
        __syncthreads();

        #pragma unroll
        for (int qq = 0; qq < QCHUNK; qq++) {
            ulonglong2 ap = *(const ulonglong2*)&at[qq][tx * 4];
            ull v0 = vd[ty * 2 + 0][qq];
            ull v1 = vd[ty * 2 + 1][qq];
            acc[0][0] = f32x2_fma(v0, ap.x, acc[0][0]);
            acc[0][1] = f32x2_fma(v0, ap.y, acc[0][1]);
            acc[1][0] = f32x2_fma(v1, ap.x, acc[1][0]);
            acc[1][1] = f32x2_fma(v1, ap.y, acc[1][1]);
        }
        __syncthreads();
    }

    float* pb = g_partial + ((size_t)s * BATCH + b) * CHAN * NTOK;
    const int kg = k0 + tx * 4;
    if (kg < NTOK) {                    // 784 % 4 == 0
        #pragma unroll
        for (int j = 0; j < 2; j++) {
            int cc = c0 + ty * 2 + j;
            float4 f;
            unpack2(acc[j][0], f.x, f.y);
            unpack2(acc[j][1], f.z, f.w);
            *(float4*)&pb[(size_t)cc * NTOK + kg] = f;
        }
    }
}

// ---------------------------------------------------------------------------
// Kernel 3b: out[i] = sum_s partial[s][i]  (fixed order -> deterministic)
// float4 vectorized: 200704/4 = 50176 threads.
// ---------------------------------------------------------------------------
__global__ void reduce_kernel(float* __restrict__ out)
{
    const int i = (blockIdx.x * 256 + threadIdx.x) * 4;
    const float4* p = (const float4*)g_partial;
    const int stride = (BATCH * CHAN * NTOK) / 4;   // 50176
    int i4 = i >> 2;

    float4 a = p[i4];
    float4 c = p[i4 + stride];
    a.x += c.x; a.y += c.y; a.z += c.z; a.w += c.w;
    c = p[i4 + 2 * stride];
    a.x += c.x; a.y += c.y; a.z += c.z; a.w += c.w;
    c = p[i4 + 3 * stride];
    a.x += c.x; a.y += c.y; a.z += c.z; a.w += c.w;

    *(float4*)&out[i] = a;
}

// ---------------------------------------------------------------------------
extern "C" void kernel_launch(void* const* d_in, const int* in_sizes, int n_in,
                              void* d_out, int out_size)
{
    const float* q = (const float*)d_in[0];
    const float* k = (const float*)d_in[1];
    const float* v = (const float*)d_in[2];

    float* out_ptr  = (float*)d_out;                         // [B, C, N]
    float* attn_ptr = out_ptr + (size_t)BATCH * CHAN * NTOK; // [B, N, N]

    dim3 g1((NTOK + 63) / 64, (NTOK + 31) / 32, BATCH);      // 13 x 25 x 2 = 650
    l1_logits_kernel<<<g1, 256>>>(q, k, attn_ptr);

    softmax_kernel<<<(BATCH * NTOK) / 8, 256>>>(attn_ptr);   // 196 blocks

    dim3 g3((NTOK + 63) / 64, CHAN / 32, BATCH * SPLITS);    // 13 x 4 x 8 = 416
    out_gemm_partial_kernel<<<g3, 256>>>(v, attn_ptr);

    reduce_kernel<<<(BATCH * CHAN * NTOK) / (256 * 4), 256>>>(out_ptr);  // 196 blocks
}